// round 3
// baseline (speedup 1.0000x reference)
#include <cuda_runtime.h>

#define B_  256
#define T_  500
#define I_  700
#define O_  400
#define M_  (B_ * T_)          // 128000 GEMM rows

// scratch for h = inputs @ W^T   [M_, O_] row-major == [B,T,O]
__device__ float g_h[(size_t)M_ * O_];

#define BM 128
#define BN 64
#define BK 16

// Kahan-compensated SGEMM: h[m,n] = sum_k A[m,k] * W[n,k], with per-output
// compensation register. Error ~ O(u) independent of K -> h is as close to
// the correctly-rounded value as fp32 allows, minimizing divergence from ANY
// reference accumulation order.
__global__ __launch_bounds__(256) void snn_gemm_kahan_kernel(const float* __restrict__ A,
                                                             const float* __restrict__ Wm) {
    __shared__ float As[BK][BM + 4];
    __shared__ float Bs[BK][BN + 4];

    const int K = I_;
    const int N = O_;
    const int bm = blockIdx.x * BM;
    const int bn = blockIdx.y * BN;
    const int tid = threadIdx.x;
    const int tx = tid & 15;   // N direction, 4 cols each
    const int ty = tid >> 4;   // M direction, 8 rows each

    float acc[8][4];
    float cmp[8][4];
    #pragma unroll
    for (int i = 0; i < 8; i++)
        #pragma unroll
        for (int j = 0; j < 4; j++) { acc[i][j] = 0.0f; cmp[i][j] = 0.0f; }

    for (int k0 = 0; k0 < K; k0 += BK) {
        // ---- load A tile: 128 rows x 16 k, 2 float4 per thread ----
        #pragma unroll
        for (int i = 0; i < 2; i++) {
            int q   = tid + i * 256;
            int row = q >> 2;            // 0..127
            int kq  = (q & 3) * 4;       // 0,4,8,12
            const float* src = A + (size_t)(bm + row) * K + k0 + kq;
            float4 v;
            if (k0 + kq + 3 < K) {
                v = *reinterpret_cast<const float4*>(src);
            } else {
                v.x = (k0 + kq + 0 < K) ? src[0] : 0.0f;
                v.y = (k0 + kq + 1 < K) ? src[1] : 0.0f;
                v.z = (k0 + kq + 2 < K) ? src[2] : 0.0f;
                v.w = (k0 + kq + 3 < K) ? src[3] : 0.0f;
            }
            As[kq + 0][row] = v.x;
            As[kq + 1][row] = v.y;
            As[kq + 2][row] = v.z;
            As[kq + 3][row] = v.w;
        }
        // ---- load W tile: 64 rows x 16 k, 1 float4 per thread ----
        {
            int q   = tid;
            int row = q >> 2;            // 0..63
            int kq  = (q & 3) * 4;
            int n   = bn + row;
            float4 v = make_float4(0.f, 0.f, 0.f, 0.f);
            if (n < N) {
                const float* src = Wm + (size_t)n * K + k0 + kq;
                if (k0 + kq + 3 < K) {
                    v = *reinterpret_cast<const float4*>(src);
                } else {
                    v.x = (k0 + kq + 0 < K) ? src[0] : 0.0f;
                    v.y = (k0 + kq + 1 < K) ? src[1] : 0.0f;
                    v.z = (k0 + kq + 2 < K) ? src[2] : 0.0f;
                    v.w = (k0 + kq + 3 < K) ? src[3] : 0.0f;
                }
            }
            Bs[kq + 0][row] = v.x;
            Bs[kq + 1][row] = v.y;
            Bs[kq + 2][row] = v.z;
            Bs[kq + 3][row] = v.w;
        }
        __syncthreads();

        // ---- compute: Kahan per accumulator ----
        // y = fma(a, b, -c)      (product with compensation folded in)
        // t = s + y
        // c = (t - s) - y
        // s = t
        #pragma unroll
        for (int kk = 0; kk < BK; kk++) {
            float4 a0 = *reinterpret_cast<const float4*>(&As[kk][ty * 8]);
            float4 a1 = *reinterpret_cast<const float4*>(&As[kk][ty * 8 + 4]);
            float4 bb = *reinterpret_cast<const float4*>(&Bs[kk][tx * 4]);
            float a[8] = {a0.x, a0.y, a0.z, a0.w, a1.x, a1.y, a1.z, a1.w};
            float b[4] = {bb.x, bb.y, bb.z, bb.w};
            #pragma unroll
            for (int i = 0; i < 8; i++) {
                #pragma unroll
                for (int j = 0; j < 4; j++) {
                    float y = __fmaf_rn(a[i], b[j], -cmp[i][j]);
                    float t = __fadd_rn(acc[i][j], y);
                    cmp[i][j] = __fadd_rn(__fadd_rn(t, -acc[i][j]), -y);
                    acc[i][j] = t;
                }
            }
        }
        __syncthreads();
    }

    // ---- store ----
    #pragma unroll
    for (int i = 0; i < 8; i++) {
        int m = bm + ty * 8 + i;
        float* dst = g_h + (size_t)m * N;
        #pragma unroll
        for (int j = 0; j < 4; j++) {
            int n = bn + tx * 4 + j;
            if (n < N) dst[n] = acc[i][j];
        }
    }
}

// One thread per (b, o) neuron; sequential over t.
// Fused (fma) variant: XLA CPU fast-math contracts mul+add -> fmuladd.
__global__ __launch_bounds__(256) void snn_scan_kernel(float* __restrict__ out) {
    int idx = blockIdx.x * blockDim.x + threadIdx.x;
    if (idx >= B_ * O_) return;
    int b = idx / O_;
    int o = idx - b * O_;

    const float* hp = g_h + (size_t)b * T_ * O_ + o;
    float* op = out + (size_t)b * T_ * O_ + o;

    float syn = 0.0f, mem = 0.0f;
    #pragma unroll 4
    for (int t = 0; t < T_; t++) {
        float ht = __ldg(hp + (size_t)t * O_);
        float s  = (mem > 1.0f) ? 1.0f : 0.0f;
        op[(size_t)t * O_] = s;
        float nsyn = __fmaf_rn(0.9f, syn, ht);
        float bmv  = __fmaf_rn(0.85f, mem, syn);
        mem = __fmul_rn(bmv, __fadd_rn(1.0f, -s));
        syn = nsyn;
    }
}

extern "C" void kernel_launch(void* const* d_in, const int* in_sizes, int n_in,
                              void* d_out, int out_size) {
    const float* inputs = (const float*)d_in[0];  // [256,500,700] f32
    const float* W      = (const float*)d_in[1];  // [400,700]     f32
    float* out          = (float*)d_out;          // [256,500,400] f32

    dim3 ggrid((M_ + BM - 1) / BM, (O_ + BN - 1) / BN);   // 1000 x 7
    snn_gemm_kahan_kernel<<<ggrid, 256>>>(inputs, W);

    int n_neurons = B_ * O_;                               // 102400
    snn_scan_kernel<<<(n_neurons + 255) / 256, 256>>>(out);
}